// round 16
// baseline (speedup 1.0000x reference)
#include <cuda_runtime.h>
#include <math.h>
#include <stdint.h>

#define N_PAT 4096
#define DIM   256
#define EPSV  1e-8f
#define RBLK  16                  // rows per prep block
#define NRB   (N_PAT / RBLK)      // 256 row-blocks per modality
#define NPREP (4 * NRB)           // 1024 prep blocks
#define NBLK  (NPREP + 1)         // + cox block
#define NBKT  4096
#define FXSCALE 262144.0f         // 2^18 fixed-point for cox histogram (u32)
#define FXU     16777216.0f       // 2^24 fixed-point for u accumulators

// ---------------- static scratch ----------------
__device__ unsigned long long g_uFx[4 * DIM];   // per (mod,col) fixed-point u sum
__device__ float2 g_vw[NPREP];                  // per (mod,rowblock) (V,W)
__device__ float  g_coxsum, g_efsum;
__device__ int    g_count;                      // arrival counter (reset by last block)

// ---------------- cold combine tail (registers isolated via noinline) ----------------
__device__ __noinline__ void combine_tail(const int* __restrict__ mptr,
                                          float* __restrict__ out) {
    __shared__ float sU[8];
    __shared__ float sVW[64];      // [quantity 0..7][warp 0..7]
    int tid = threadIdx.x;
    int w = tid >> 5, lane = tid & 31;

    // total U^2 (additive over mods and cols)
    float us = 0.0f;
#pragma unroll
    for (int m = 0; m < 4; m++) {
        int idx = (m << 8) + tid;
        float u = (float)((long long)g_uFx[idx]) * (1.0f / FXU);
        us += u * u;
        g_uFx[idx] = 0ull;          // reset for next graph replay
    }
#pragma unroll
    for (int o = 16; o > 0; o >>= 1) us += __shfl_xor_sync(0xffffffffu, us, o);
    if (lane == 0) sU[w] = us;

    // per-mod V, W: thread t handles rowblock t of each mod (NRB == 256)
    float2 v0 = g_vw[tid];
    float2 v1 = g_vw[tid + 256];
    float2 v2 = g_vw[tid + 512];
    float2 v3 = g_vw[tid + 768];
    float q[8] = { v0.x, v0.y, v1.x, v1.y, v2.x, v2.y, v3.x, v3.y };
#pragma unroll
    for (int k = 0; k < 8; k++) {
#pragma unroll
        for (int o = 16; o > 0; o >>= 1)
            q[k] += __shfl_xor_sync(0xffffffffu, q[k], o);
    }
    if (lane == 0) {
#pragma unroll
        for (int k = 0; k < 8; k++) sVW[k * 8 + w] = q[k];
    }
    __syncthreads();

    if (tid == 0) {
        float U2tot = 0.0f;
#pragma unroll
        for (int i = 0; i < 8; i++) U2tot += sU[i];

        double sim = 0.0;
#pragma unroll
        for (int m = 0; m < 4; m++) {
            float V = 0.0f, W = 0.0f;
#pragma unroll
            for (int i = 0; i < 8; i++) {
                V += sVW[(2 * m) * 8 + i];
                W += sVW[(2 * m + 1) * 8 + i];
            }
            sim += (double)W * (double)V;
        }
        int iv = mptr[0];
        float margin = (iv > -1000000 && iv < 1000000) ? (float)iv : __int_as_float(iv);
        sim += (double)margin * (double)N_PAT * (double)(N_PAT - 1) - (double)U2tot;

        double cox = -(double)g_coxsum / (double)g_efsum;
        out[0] = (float)(sim + cox);
        g_count = 0;                // reset for next graph replay
    }
}

// =================== single kernel: cox + prep + last-block combine ===================
__global__ void __launch_bounds__(256, 7)
main_kernel(const float* __restrict__ h, const int* __restrict__ t,
            const int* __restrict__ e,
            const float* __restrict__ eb0, const float* __restrict__ eb1,
            const float* __restrict__ eb2, const float* __restrict__ eb3,
            const int* __restrict__ mptr, float* __restrict__ out) {
    __shared__ __align__(16) unsigned int bkt[NBKT];   // 16KB; cox block only
    __shared__ float smf[2048];
    __shared__ float snm[8], sww[8];
    __shared__ int s_last;
    float* S = (float*)bkt;

    int tid = threadIdx.x;
    int w = tid >> 5, lane = tid & 31;

    if (blockIdx.x == 0) {
        // ================= cox: histogram + warp-suffix-scan + lookup =================
#pragma unroll
        for (int k = 0; k < 16; k++) bkt[tid + k * 256] = 0u;
        __syncthreads();

        int   tv[16];
        float hv[16];
#pragma unroll
        for (int k = 0; k < 16; k++) {
            int i = tid + k * 256;
            tv[k] = t[i] & (NBKT - 1);
            hv[k] = h[i];
            unsigned int q = (unsigned int)(expf(hv[k]) * FXSCALE);
            atomicAdd(&bkt[tv[k]], q);
        }
        __syncthreads();

        float b[16];
        float cs = 0.0f;
#pragma unroll
        for (int j = 0; j < 16; j++) {
            b[j] = (float)bkt[tid * 16 + j] * (1.0f / FXSCALE);
            cs += b[j];
        }
        float suf = cs;
#pragma unroll
        for (int o = 1; o < 32; o <<= 1) {
            float v = __shfl_down_sync(0xffffffffu, suf, o);
            if (lane + o < 32) suf += v;
        }
        if (lane == 0) snm[w] = suf;
        __syncthreads();

        float wse = 0.0f;
        for (int ww = w + 1; ww < 8; ww++) wse += snm[ww];
        float excl = wse + (suf - cs);
        float s = excl;
#pragma unroll
        for (int j = 15; j >= 0; j--) {
            s += b[j];
            S[tid * 16 + j] = s;
        }
        __syncthreads();

        float cp = 0.0f, ef = 0.0f;
#pragma unroll
        for (int k = 0; k < 16; k++) {
            int i = tid + k * 256;
            int ei = e[i];
            ef += (float)ei;
            if (ei) cp += hv[k] - logf(S[tv[k]]);
        }
#pragma unroll
        for (int o = 16; o > 0; o >>= 1) {
            cp += __shfl_xor_sync(0xffffffffu, cp, o);
            ef += __shfl_xor_sync(0xffffffffu, ef, o);
        }
        if (lane == 0) { snm[w] = cp; sww[w] = ef; }
        __syncthreads();
        if (tid == 0) {
            float tc = 0.0f, te = 0.0f;
#pragma unroll
            for (int i = 0; i < 8; i++) { tc += snm[i]; te += sww[i]; }
            g_coxsum = tc; g_efsum = te;
        }
    } else {
        // ================= prep: 16 rows, 2 per warp =================
        int pb  = blockIdx.x - 1;
        int mod = pb >> 8;
        int rb  = pb & 255;
        int r0  = rb * RBLK;
        const float* base = (mod == 0) ? eb0 : (mod == 1) ? eb1
                          : (mod == 2) ? eb2 : eb3;

        float4 va[2], vb[2];
#pragma unroll
        for (int rr = 0; rr < 2; rr++) {
            const float4* src = (const float4*)(base + (size_t)(r0 + w * 2 + rr) * DIM);
            va[rr] = src[lane];
            vb[rr] = src[lane + 32];
        }

        float4 acc0 = make_float4(0.f, 0.f, 0.f, 0.f);
        float4 acc1 = make_float4(0.f, 0.f, 0.f, 0.f);
        float nmW = 0.0f, wW = 0.0f;
#pragma unroll
        for (int rr = 0; rr < 2; rr++) {
            float4 v0 = va[rr], v1 = vb[rr];
            float x0 = __shfl_sync(0xffffffffu, v0.x, 0);
            bool eq = (v0.x == x0) && (v0.y == x0) && (v0.z == x0) && (v0.w == x0) &&
                      (v1.x == x0) && (v1.y == x0) && (v1.z == x0) && (v1.w == x0);
            bool miss = (__ballot_sync(0xffffffffu, eq) == 0xffffffffu);

            float ss = v0.x*v0.x + v0.y*v0.y + v0.z*v0.z + v0.w*v0.w
                     + v1.x*v1.x + v1.y*v1.y + v1.z*v1.z + v1.w*v1.w;
#pragma unroll
            for (int o = 16; o > 0; o >>= 1) ss += __shfl_xor_sync(0xffffffffu, ss, o);

            float den = fmaxf(sqrtf(ss), EPSV);
            float inv = miss ? 0.0f : (1.0f / den);
            if (!miss) { nmW += 1.0f; wW += ss / (den * den); }

            acc0.x += v0.x * inv; acc0.y += v0.y * inv;
            acc0.z += v0.z * inv; acc0.w += v0.w * inv;
            acc1.x += v1.x * inv; acc1.y += v1.y * inv;
            acc1.z += v1.z * inv; acc1.w += v1.w * inv;
        }

        float* row = smf + w * 256;
        *(float4*)(row + lane * 4)       = acc0;
        *(float4*)(row + 128 + lane * 4) = acc1;
        if (lane == 0) { snm[w] = nmW; sww[w] = wW; }
        __syncthreads();

        float u = 0.0f;
#pragma unroll
        for (int ww = 0; ww < 8; ww++) u += smf[ww * 256 + tid];
        // deterministic fixed-point accumulation (integer adds commute)
        long long q = (long long)llrintf(u * FXU);
        atomicAdd(&g_uFx[(mod << 8) + tid], (unsigned long long)q);

        if (tid == 0) {
            float V = 0.0f, W = 0.0f;
#pragma unroll
            for (int i = 0; i < 8; i++) { V += snm[i]; W += sww[i]; }
            g_vw[pb] = make_float2(V, W);
        }
    }

    // =================== last-arriving block: combine ===================
    __threadfence();
    if (tid == 0) {
        int c = atomicAdd(&g_count, 1);
        s_last = (c == NBLK - 1);
    }
    __syncthreads();
    if (!s_last) return;

    combine_tail(mptr, out);
}

// ---------------- launch ----------------
extern "C" void kernel_launch(void* const* d_in, const int* in_sizes, int n_in,
                              void* d_out, int out_size) {
    const float* h   = (const float*)d_in[0];
    const int*   t   = (const int*)d_in[1];
    const int*   e   = (const int*)d_in[2];
    const float* eb0 = (const float*)d_in[3];
    const float* eb1 = (const float*)d_in[4];
    const float* eb2 = (const float*)d_in[5];
    const float* eb3 = (const float*)d_in[6];
    const int*   mg  = (const int*)d_in[7];
    float* out = (float*)d_out;

    main_kernel<<<NBLK, 256>>>(h, t, e, eb0, eb1, eb2, eb3, mg, out);
}